// round 5
// baseline (speedup 1.0000x reference)
#include <cuda_runtime.h>

// Output is identically zero: g = -sum((x - x)^2) == 0 elementwise, so
// w = C*g == 0 and lambda_tri = mask @ w == 0. Kernel = 64 KB zero-fill.
//
// Measurement history (wall = device + ~1.28us replay overhead):
//   R1: 16x256, 1 f4/thr -> dev 3.68, wall 4.864
//   R2: memset node      -> wall 4.864
//   R3: 1x1024, 4 f4/thr -> dev 4.35, wall 6.66  (single-SM LSU serialization)
//   R4: 32x128, 1 f4/thr -> dev 3.33, wall 4.608 (wider = faster; floor theory dead)
// R5: widest useful grid: 128 blocks x 32 threads, one warp per block, one
// STG.128 per lane. Minimal per-SM critical path, single dispatch wave.

__global__ __launch_bounds__(32, 1)
void zero_warp(float4* __restrict__ out) {
    // 128 blocks x 32 lanes = 4096 float4 = 16384 floats = 64 KB.
    out[(blockIdx.x << 5) | threadIdx.x] = make_float4(0.f, 0.f, 0.f, 0.f);
}

__global__ void zero_generic(float* __restrict__ out, int n) {
    int i = blockIdx.x * blockDim.x + threadIdx.x;
    if (i < n) out[i] = 0.f;
}

extern "C" void kernel_launch(void* const* d_in, const int* in_sizes, int n_in,
                              void* d_out, int out_size) {
    (void)d_in; (void)in_sizes; (void)n_in;
    if (out_size == 16384) {
        zero_warp<<<128, 32>>>((float4*)d_out);
    } else {
        int threads = 256;
        int blocks = (out_size + threads - 1) / threads;
        zero_generic<<<blocks, threads>>>((float*)d_out, out_size);
    }
}

// round 6
// speedup vs baseline: 1.3252x; 1.3252x over previous
#include <cuda_runtime.h>

// Output is identically zero: g = -sum((x - x)^2) == 0 elementwise, so
// w = C*g == 0 and lambda_tri = mask @ w == 0. Kernel = 64 KB zero-fill.
//
// Grid-shape U-curve measured (device dur, 1 STG.128/thread unless noted):
//   1x1024 (4/thr): 4.35us   (store serialization on one SM)
//   16x256:         3.68us
//   32x128:         3.33us   <- best so far (wall 4.608)
//   128x32:         4.54us   (per-block dispatch overhead dominates)
// R6: midpoint probe 64x64.

__global__ __launch_bounds__(64, 1)
void zero_64x64(float4* __restrict__ out) {
    // 64 blocks x 64 threads = 4096 float4 = 16384 floats = 64 KB.
    out[(blockIdx.x << 6) | threadIdx.x] = make_float4(0.f, 0.f, 0.f, 0.f);
}

__global__ void zero_generic(float* __restrict__ out, int n) {
    int i = blockIdx.x * blockDim.x + threadIdx.x;
    if (i < n) out[i] = 0.f;
}

extern "C" void kernel_launch(void* const* d_in, const int* in_sizes, int n_in,
                              void* d_out, int out_size) {
    (void)d_in; (void)in_sizes; (void)n_in;
    if (out_size == 16384) {
        zero_64x64<<<64, 64>>>((float4*)d_out);
    } else {
        int threads = 256;
        int blocks = (out_size + threads - 1) / threads;
        zero_generic<<<blocks, threads>>>((float*)d_out, out_size);
    }
}